// round 16
// baseline (speedup 1.0000x reference)
#include <cuda_runtime.h>
#include <math.h>

// Shapes are fixed by the problem instance.
#define Bn    1024
#define Tn    1024
#define Dn    256
#define DINn  256
#define Mn    10
#define NB    4                      // batches per compute block
#define NCOMPUTE (Bn / NB)           // 256 compute blocks

__device__ __forceinline__ float sigmoidf_(float v) { return 1.0f / (1.0f + expf(-v)); }

// Compute-only kernel: runs AFTER the bulk memcpy has populated out_hist.
// Writes h, y, and overwrites the t==ci rows of out_hist with h.
__global__ __launch_bounds__(256)
void bjrnn_compute(const float* __restrict__ x,
                   const float* __restrict__ hist,
                   const float* __restrict__ Win, const float* __restrict__ bin,
                   const float* __restrict__ Wk,  const float* __restrict__ bk,
                   const float* __restrict__ Wv,  const float* __restrict__ bv,
                   const float* __restrict__ Wbl, const float* __restrict__ bbl,
                   const int* __restrict__ jumps,
                   const int* __restrict__ cidx,
                   float* __restrict__ out)
{
    const int tid = threadIdx.x;
    const int ci  = cidx ? cidx[0] : 513;
    float* __restrict__ out_h    = out;
    float* __restrict__ out_y    = out + Bn * Dn;
    float* __restrict__ out_hist = out + 2 * Bn * Dn;

    // Algebraic identities:
    //   scores_m = (H_m . u + q.b_k) / 16,  u_e = sum_d Wk[e,d] q_d
    //   rs       = Hbar @ Wv + bv,          Hbar = sum_m attn_m H_m
    __shared__ float xs[NB][DINn];
    __shared__ float qs[NB][Dn];
    __shared__ float us[NB][Dn];
    __shared__ float hb[NB][Dn];
    __shared__ float hs[NB][Dn];
    __shared__ float sc[NB][Mn];
    __shared__ float red[NB][8];
    __shared__ float qb[NB];
    __shared__ int   idxm[Mn];

    const int lane = tid & 31;
    const int warp = tid >> 5;
    const int b0   = blockIdx.x * NB;

    if (tid < Mn) {
        int jmp = jumps ? jumps[tid] : (1 << tid);
        int v = ci - jmp;
        idxm[tid] = v < 0 ? 0 : v;
    }
    #pragma unroll
    for (int j = 0; j < NB; j++)
        xs[j][tid] = x[(b0 + j) * DINn + tid];
    __syncthreads();

    // phase 1: q = x @ Win + bin
    {
        float acc[NB];
        float bi = bin[tid];
        #pragma unroll
        for (int j = 0; j < NB; j++) acc[j] = bi;
        #pragma unroll 4
        for (int e = 0; e < DINn; e++) {
            float w = Win[e * Dn + tid];
            #pragma unroll
            for (int j = 0; j < NB; j++) acc[j] = fmaf(xs[j][e], w, acc[j]);
        }
        #pragma unroll
        for (int j = 0; j < NB; j++) qs[j][tid] = acc[j];
    }
    __syncthreads();

    // qb[j] = q[j] . bk
    {
        float bkv = bk[tid];
        #pragma unroll
        for (int j = 0; j < NB; j++) {
            float t = qs[j][tid] * bkv;
            #pragma unroll
            for (int o = 16; o > 0; o >>= 1) t += __shfl_down_sync(0xffffffffu, t, o);
            if (lane == 0) red[j][warp] = t;
        }
        __syncthreads();
        if (tid < NB) {
            float s = 0.f;
            #pragma unroll
            for (int w = 0; w < 8; w++) s += red[tid][w];
            qb[tid] = s;
        }
        __syncthreads();
    }

    // phase 2: u[j][e] = sum_d Wk[e,d] * q[j][d]  (warp per e; coalesced rows)
    for (int i = 0; i < 32; i++) {
        int e = warp * 32 + i;
        const float* __restrict__ row = Wk + e * Dn;
        float p[NB] = {0.f, 0.f, 0.f, 0.f};
        #pragma unroll
        for (int k = 0; k < 8; k++) {
            int d = lane + k * 32;
            float w = row[d];
            #pragma unroll
            for (int j = 0; j < NB; j++) p[j] = fmaf(w, qs[j][d], p[j]);
        }
        #pragma unroll
        for (int j = 0; j < NB; j++) {
            #pragma unroll
            for (int o = 16; o > 0; o >>= 1) p[j] += __shfl_down_sync(0xffffffffu, p[j], o);
        }
        if (lane == 0) {
            #pragma unroll
            for (int j = 0; j < NB; j++) us[j][e] = p[j];
        }
    }
    __syncthreads();

    // phase 3: scores[j][m] = (H[b, idx_m] . u[j] + qb[j]) / 16
    for (int m = warp; m < Mn; m += 8) {
        #pragma unroll
        for (int j = 0; j < NB; j++) {
            const float* __restrict__ Hrow = hist + ((b0 + j) * Tn + idxm[m]) * Dn;
            float p = 0.f;
            #pragma unroll
            for (int k = 0; k < 8; k++) {
                int d = lane + k * 32;
                p = fmaf(Hrow[d], us[j][d], p);
            }
            #pragma unroll
            for (int o = 16; o > 0; o >>= 1) p += __shfl_down_sync(0xffffffffu, p, o);
            if (lane == 0) sc[j][m] = (p + qb[j]) * 0.0625f;
        }
    }
    __syncthreads();

    // phase 4: softmax over m
    if (tid < NB) {
        float mx = sc[tid][0];
        #pragma unroll
        for (int m = 1; m < Mn; m++) mx = fmaxf(mx, sc[tid][m]);
        float s = 0.f;
        #pragma unroll
        for (int m = 0; m < Mn; m++) { float e2 = expf(sc[tid][m] - mx); sc[tid][m] = e2; s += e2; }
        float inv = 1.0f / s;
        #pragma unroll
        for (int m = 0; m < Mn; m++) sc[tid][m] *= inv;
    }
    __syncthreads();

    // phase 5: Hbar[j][e] = sum_m attn[j][m] * H[b, idx_m, e]
    #pragma unroll
    for (int j = 0; j < NB; j++) {
        const float* __restrict__ base = hist + (b0 + j) * Tn * Dn;
        float a = 0.f;
        #pragma unroll
        for (int m = 0; m < Mn; m++)
            a = fmaf(sc[j][m], base[idxm[m] * Dn + tid], a);
        hb[j][tid] = a;
    }
    __syncthreads();

    // phase 6: rs = Hbar @ Wv + bv;  h = sigmoid(q + rs);  write h + slot ci
    {
        float acc[NB];
        float bvv = bv[tid];
        #pragma unroll
        for (int j = 0; j < NB; j++) acc[j] = bvv;
        #pragma unroll 4
        for (int e = 0; e < Dn; e++) {
            float w = Wv[e * Dn + tid];
            #pragma unroll
            for (int j = 0; j < NB; j++) acc[j] = fmaf(hb[j][e], w, acc[j]);
        }
        #pragma unroll
        for (int j = 0; j < NB; j++) {
            float hv = sigmoidf_(qs[j][tid] + acc[j]);
            hs[j][tid] = hv;
            out_h[(b0 + j) * Dn + tid] = hv;
            out_hist[((size_t)(b0 + j) * Tn + ci) * Dn + tid] = hv;
        }
    }
    __syncthreads();

    // phase 7: y = sigmoid(h @ Wbl + bbl + h)
    {
        float acc[NB];
        float bb = bbl[tid];
        #pragma unroll
        for (int j = 0; j < NB; j++) acc[j] = bb;
        #pragma unroll 4
        for (int e = 0; e < Dn; e++) {
            float w = Wbl[e * Dn + tid];
            #pragma unroll
            for (int j = 0; j < NB; j++) acc[j] = fmaf(hs[j][e], w, acc[j]);
        }
        #pragma unroll
        for (int j = 0; j < NB; j++)
            out_y[(b0 + j) * Dn + tid] = sigmoidf_(acc[j] + hs[j][tid]);
    }
}

extern "C" void kernel_launch(void* const* d_in, const int* in_sizes, int n_in,
                              void* d_out, int out_size)
{
    (void)in_sizes; (void)out_size;
    const float* x    = (const float*)d_in[0];
    const float* hist = (const float*)d_in[1];
    const float* Win  = (const float*)d_in[2];
    const float* bin  = (const float*)d_in[3];
    const float* Wk   = (const float*)d_in[4];
    const float* bk   = (const float*)d_in[5];
    const float* Wv   = (const float*)d_in[6];
    const float* bv   = (const float*)d_in[7];
    const float* Wbl  = (const float*)d_in[8];
    const float* bbl  = (const float*)d_in[9];
    const int* jumps  = (n_in > 10) ? (const int*)d_in[10] : nullptr;
    const int* cidx   = (n_in > 11) ? (const int*)d_in[11] : nullptr;

    float* out      = (float*)d_out;
    float* out_hist = out + 2 * (size_t)Bn * Dn;

    // 1) Bulk history copy via the driver's tuned D2D path (graph memcpy node).
    cudaMemcpyAsync(out_hist, hist, (size_t)Bn * Tn * Dn * sizeof(float),
                    cudaMemcpyDeviceToDevice);

    // 2) Compute h, y; overwrite the t==ci rows of out_hist (same stream -> ordered).
    bjrnn_compute<<<NCOMPUTE, 256>>>(x, hist, Win, bin, Wk, bk, Wv, bv, Wbl, bbl,
                                     jumps, cidx, out);
}

// round 17
// speedup vs baseline: 2.5082x; 2.5082x over previous
#include <cuda_runtime.h>
#include <math.h>

// Shapes are fixed by the problem instance.
#define Bn    1024
#define Tn    1024
#define Dn    256
#define DINn  256
#define Mn    10
#define NB    4                      // batches per compute block
#define NCOMPUTE (Bn / NB)           // 256 compute blocks
#define NBLOCKS  1184                // 148 SMs * 8; extra blocks exit via stealing
#define NF4      (Bn * Tn * (Dn / 4))      // 67,108,864 float4s
#define CHUNK    2048                // float4s per chunk = one U=8 pass of a block
#define NCHUNK   (NF4 / CHUNK)       // 32768 chunks

__device__ unsigned int g_chunk_ctr;

__global__ void bjrnn_reset() { g_chunk_ctr = 0u; }

__device__ __forceinline__ float sigmoidf_(float v) { return 1.0f / (1.0f + expf(-v)); }

__global__ __launch_bounds__(256)
void bjrnn_fused(const float* __restrict__ x,
                 const float* __restrict__ hist,
                 const float* __restrict__ Win, const float* __restrict__ bin,
                 const float* __restrict__ Wk,  const float* __restrict__ bk,
                 const float* __restrict__ Wv,  const float* __restrict__ bv,
                 const float* __restrict__ Wbl, const float* __restrict__ bbl,
                 const int* __restrict__ jumps,
                 const int* __restrict__ cidx,
                 float* __restrict__ out)
{
    const int tid = threadIdx.x;
    const int ci  = cidx ? cidx[0] : 513;
    float* __restrict__ out_h    = out;
    float* __restrict__ out_y    = out + Bn * Dn;
    float* __restrict__ out_hist = out + 2 * Bn * Dn;

    __shared__ unsigned chunk_s;

    // ------------------------------------------------------------------
    // Compute blocks (0..NCOMPUTE-1): NB=4 batches each, then fall through
    // to the copy-stealing loop. Algebraic identities:
    //   scores_m = (H_m . u + q.b_k) / 16,  u_e = sum_d Wk[e,d] q_d
    //   rs       = Hbar @ Wv + bv,          Hbar = sum_m attn_m H_m
    // ------------------------------------------------------------------
    if (blockIdx.x < NCOMPUTE) {
        __shared__ float xs[NB][DINn];
        __shared__ float qs[NB][Dn];
        __shared__ float us[NB][Dn];
        __shared__ float hb[NB][Dn];
        __shared__ float hs[NB][Dn];
        __shared__ float sc[NB][Mn];
        __shared__ float red[NB][8];
        __shared__ float qb[NB];
        __shared__ int   idxm[Mn];

        const int lane = tid & 31;
        const int warp = tid >> 5;
        const int b0   = blockIdx.x * NB;

        if (tid < Mn) {
            int jmp = jumps ? jumps[tid] : (1 << tid);
            int v = ci - jmp;
            idxm[tid] = v < 0 ? 0 : v;
        }
        #pragma unroll
        for (int j = 0; j < NB; j++)
            xs[j][tid] = x[(b0 + j) * DINn + tid];
        __syncthreads();

        // phase 1: q = x @ Win + bin
        {
            float acc[NB];
            float bi = bin[tid];
            #pragma unroll
            for (int j = 0; j < NB; j++) acc[j] = bi;
            #pragma unroll 4
            for (int e = 0; e < DINn; e++) {
                float w = Win[e * Dn + tid];
                #pragma unroll
                for (int j = 0; j < NB; j++) acc[j] = fmaf(xs[j][e], w, acc[j]);
            }
            #pragma unroll
            for (int j = 0; j < NB; j++) qs[j][tid] = acc[j];
        }
        __syncthreads();

        // qb[j] = q[j] . bk
        {
            float bkv = bk[tid];
            #pragma unroll
            for (int j = 0; j < NB; j++) {
                float t = qs[j][tid] * bkv;
                #pragma unroll
                for (int o = 16; o > 0; o >>= 1) t += __shfl_down_sync(0xffffffffu, t, o);
                if (lane == 0) red[j][warp] = t;
            }
            __syncthreads();
            if (tid < NB) {
                float s = 0.f;
                #pragma unroll
                for (int w = 0; w < 8; w++) s += red[tid][w];
                qb[tid] = s;
            }
            __syncthreads();
        }

        // phase 2: u[j][e] = sum_d Wk[e,d] * q[j][d]  (warp per e)
        for (int i = 0; i < 32; i++) {
            int e = warp * 32 + i;
            const float* __restrict__ row = Wk + e * Dn;
            float p[NB] = {0.f, 0.f, 0.f, 0.f};
            #pragma unroll
            for (int k = 0; k < 8; k++) {
                int d = lane + k * 32;
                float w = row[d];
                #pragma unroll
                for (int j = 0; j < NB; j++) p[j] = fmaf(w, qs[j][d], p[j]);
            }
            #pragma unroll
            for (int j = 0; j < NB; j++) {
                #pragma unroll
                for (int o = 16; o > 0; o >>= 1) p[j] += __shfl_down_sync(0xffffffffu, p[j], o);
            }
            if (lane == 0) {
                #pragma unroll
                for (int j = 0; j < NB; j++) us[j][e] = p[j];
            }
        }
        __syncthreads();

        // phase 3: scores[j][m] = (H[b, idx_m] . u[j] + qb[j]) / 16
        for (int m = warp; m < Mn; m += 8) {
            #pragma unroll
            for (int j = 0; j < NB; j++) {
                const float* __restrict__ Hrow = hist + ((b0 + j) * Tn + idxm[m]) * Dn;
                float p = 0.f;
                #pragma unroll
                for (int k = 0; k < 8; k++) {
                    int d = lane + k * 32;
                    p = fmaf(Hrow[d], us[j][d], p);
                }
                #pragma unroll
                for (int o = 16; o > 0; o >>= 1) p += __shfl_down_sync(0xffffffffu, p, o);
                if (lane == 0) sc[j][m] = (p + qb[j]) * 0.0625f;
            }
        }
        __syncthreads();

        // phase 4: softmax over m
        if (tid < NB) {
            float mx = sc[tid][0];
            #pragma unroll
            for (int m = 1; m < Mn; m++) mx = fmaxf(mx, sc[tid][m]);
            float s = 0.f;
            #pragma unroll
            for (int m = 0; m < Mn; m++) { float e2 = expf(sc[tid][m] - mx); sc[tid][m] = e2; s += e2; }
            float inv = 1.0f / s;
            #pragma unroll
            for (int m = 0; m < Mn; m++) sc[tid][m] *= inv;
        }
        __syncthreads();

        // phase 5: Hbar[j][e] = sum_m attn[j][m] * H[b, idx_m, e]
        #pragma unroll
        for (int j = 0; j < NB; j++) {
            const float* __restrict__ base = hist + (b0 + j) * Tn * Dn;
            float a = 0.f;
            #pragma unroll
            for (int m = 0; m < Mn; m++)
                a = fmaf(sc[j][m], base[idxm[m] * Dn + tid], a);
            hb[j][tid] = a;
        }
        __syncthreads();

        // phase 6: rs = Hbar @ Wv + bv;  h = sigmoid(q + rs);  write h + slot ci
        {
            float acc[NB];
            float bvv = bv[tid];
            #pragma unroll
            for (int j = 0; j < NB; j++) acc[j] = bvv;
            #pragma unroll 4
            for (int e = 0; e < Dn; e++) {
                float w = Wv[e * Dn + tid];
                #pragma unroll
                for (int j = 0; j < NB; j++) acc[j] = fmaf(hb[j][e], w, acc[j]);
            }
            #pragma unroll
            for (int j = 0; j < NB; j++) {
                float hv = sigmoidf_(qs[j][tid] + acc[j]);
                hs[j][tid] = hv;
                out_h[(b0 + j) * Dn + tid] = hv;
                out_hist[((b0 + j) * Tn + ci) * Dn + tid] = hv;
            }
        }
        __syncthreads();

        // phase 7: y = sigmoid(h @ Wbl + bbl + h)
        {
            float acc[NB];
            float bb = bbl[tid];
            #pragma unroll
            for (int j = 0; j < NB; j++) acc[j] = bb;
            #pragma unroll 4
            for (int e = 0; e < Dn; e++) {
                float w = Wbl[e * Dn + tid];
                #pragma unroll
                for (int j = 0; j < NB; j++) acc[j] = fmaf(hs[j][e], w, acc[j]);
            }
            #pragma unroll
            for (int j = 0; j < NB; j++)
                out_y[(b0 + j) * Dn + tid] = sigmoidf_(acc[j] + hs[j][tid]);
        }
        __syncthreads();
    }

    // ------------------------------------------------------------------
    // Copy-stealing loop: ALL blocks (compute blocks join after finishing).
    // Chunk = 2048 contiguous float4 (32 KB read). Skip rows t == ci.
    // ------------------------------------------------------------------
    {
        const float4* __restrict__ src = reinterpret_cast<const float4*>(hist);
        float4* __restrict__ dst       = reinterpret_cast<float4*>(out_hist);

        for (;;) {
            if (tid == 0) chunk_s = atomicAdd(&g_chunk_ctr, 1u);
            __syncthreads();
            unsigned c = chunk_s;
            __syncthreads();          // protect chunk_s from next-round overwrite
            if (c >= NCHUNK) break;

            int base = (int)c * CHUNK;
            float4 v[8];
            #pragma unroll
            for (int k = 0; k < 8; k++) v[k] = src[base + k * 256 + tid];
            #pragma unroll
            for (int k = 0; k < 8; k++) {
                int idx = base + k * 256 + tid;
                int r = idx >> 6;                    // 64 float4 per D=256 row
                if ((r & (Tn - 1)) != ci) dst[idx] = v[k];
            }
        }
    }
}

extern "C" void kernel_launch(void* const* d_in, const int* in_sizes, int n_in,
                              void* d_out, int out_size)
{
    (void)in_sizes; (void)out_size;
    const float* x    = (const float*)d_in[0];
    const float* hist = (const float*)d_in[1];
    const float* Win  = (const float*)d_in[2];
    const float* bin  = (const float*)d_in[3];
    const float* Wk   = (const float*)d_in[4];
    const float* bk   = (const float*)d_in[5];
    const float* Wv   = (const float*)d_in[6];
    const float* bv   = (const float*)d_in[7];
    const float* Wbl  = (const float*)d_in[8];
    const float* bbl  = (const float*)d_in[9];
    const int* jumps  = (n_in > 10) ? (const int*)d_in[10] : nullptr;
    const int* cidx   = (n_in > 11) ? (const int*)d_in[11] : nullptr;

    bjrnn_reset<<<1, 1>>>();
    bjrnn_fused<<<NBLOCKS, 256>>>(x, hist, Win, bin, Wk, bk, Wv, bv, Wbl, bbl,
                                  jumps, cidx, (float*)d_out);
}